// round 5
// baseline (speedup 1.0000x reference)
#include <cuda_runtime.h>
#include <cuda_fp16.h>
#include <math.h>

// dims: VOCAB=32000 E=256 U=512 4U=2048 T=512 B=128
// LSTM partition: 8 groups x 16 CTAs; CTA = 16 batch rows x 128 gate cols (32 units)

__device__ __align__(16) __half g_embW[32000u * 2048u];  // emb@Wx+b, cols permuted u*4+gate
__device__ __align__(16) __half g_Wxr[256 * 2048];       // Wx permuted, fp16
__device__ __align__(16) __half g_Whr[512 * 2048];       // Wh permuted, fp16
__device__ __align__(16) float  g_br[2048];              // b permuted
__device__ __align__(16) __half g_hbuf[2 * 128 * 512];   // double-buffered h
__device__ unsigned g_cnt[8];                            // per-group step counters

static __device__ __forceinline__ unsigned su(const void* p) {
    return (unsigned)__cvta_generic_to_shared(p);
}
static __device__ __forceinline__ void ldsm4(unsigned* r, unsigned a) {
    asm volatile("ldmatrix.sync.aligned.m8n8.x4.shared.b16 {%0,%1,%2,%3}, [%4];\n"
        : "=r"(r[0]), "=r"(r[1]), "=r"(r[2]), "=r"(r[3]) : "r"(a));
}
static __device__ __forceinline__ void ldsm4t(unsigned* r, unsigned a) {
    asm volatile("ldmatrix.sync.aligned.m8n8.x4.trans.shared.b16 {%0,%1,%2,%3}, [%4];\n"
        : "=r"(r[0]), "=r"(r[1]), "=r"(r[2]), "=r"(r[3]) : "r"(a));
}
static __device__ __forceinline__ void mmaf(float* d, const unsigned* a, const unsigned* b) {
    asm volatile("mma.sync.aligned.m16n8k16.row.col.f32.f16.f16.f32 "
        "{%0,%1,%2,%3}, {%4,%5,%6,%7}, {%8,%9}, {%0,%1,%2,%3};\n"
        : "+f"(d[0]), "+f"(d[1]), "+f"(d[2]), "+f"(d[3])
        : "r"(a[0]), "r"(a[1]), "r"(a[2]), "r"(a[3]), "r"(b[0]), "r"(b[1]));
}

// ---------- prep: permute weights to fp16, zero state ----------
__global__ void prep_kernel(const float* __restrict__ Wx, const float* __restrict__ Wh,
                            const float* __restrict__ b) {
    int tid = blockIdx.x * blockDim.x + threadIdx.x, nth = gridDim.x * blockDim.x;
    for (int i = tid; i < 256 * 2048; i += nth) {
        int k = i >> 11, j = i & 2047, u = j >> 2, gt = j & 3;
        g_Wxr[i] = __float2half_rn(Wx[k * 2048 + gt * 512 + u]);
    }
    for (int i = tid; i < 512 * 2048; i += nth) {
        int k = i >> 11, j = i & 2047, u = j >> 2, gt = j & 3;
        g_Whr[i] = __float2half_rn(Wh[k * 2048 + gt * 512 + u]);
    }
    for (int i = tid; i < 2048; i += nth) { int u = i >> 2, gt = i & 3; g_br[i] = b[gt * 512 + u]; }
    for (int i = tid; i < 2 * 128 * 512; i += nth) g_hbuf[i] = __float2half_rn(0.f);
    if (tid < 8) g_cnt[tid] = 0u;
}

// ---------- embW = emb @ Wxr + br : CTA 128x128, K=256 ----------
__global__ __launch_bounds__(256) void embw_gemm(const float* __restrict__ emb) {
    __shared__ __align__(16) __half As[128 * 40];
    __shared__ __align__(16) __half Bs[32 * 136];
    int tid = threadIdx.x, lane = tid & 31, w = tid >> 5, wm = w >> 2, wn = w & 3;
    int m0 = blockIdx.y * 128, n0 = blockIdx.x * 128;
    float acc[4][4][4];
    #pragma unroll
    for (int i = 0; i < 4; i++)
        #pragma unroll
        for (int j = 0; j < 4; j++)
            #pragma unroll
            for (int k = 0; k < 4; k++) acc[i][j][k] = 0.f;
    unsigned sA = su(As), sB = su(Bs);
    int q = lane >> 3, l7 = lane & 7;
    for (int kt = 0; kt < 8; kt++) {
        int k0 = kt * 32;
        #pragma unroll
        for (int i = 0; i < 4; i++) {
            int idx = tid + i * 256; int r = idx >> 3, f = (idx & 7) * 4;
            float4 v = *(const float4*)(emb + (size_t)(m0 + r) * 256 + k0 + f);
            __half2* p = (__half2*)(As + r * 40 + f);
            p[0] = __floats2half2_rn(v.x, v.y); p[1] = __floats2half2_rn(v.z, v.w);
        }
        #pragma unroll
        for (int i = 0; i < 2; i++) {
            int idx = tid + i * 256; int r = idx >> 4, c = (idx & 15) * 8;
            *(uint4*)(Bs + r * 136 + c) = *(const uint4*)(g_Wxr + (size_t)(k0 + r) * 2048 + n0 + c);
        }
        __syncthreads();
        #pragma unroll
        for (int ks = 0; ks < 2; ks++) {
            unsigned a[4][4], bb[2][4];
            #pragma unroll
            for (int mt = 0; mt < 4; mt++) {
                int r = wm * 64 + mt * 16 + (q & 1) * 8 + l7, c = ks * 16 + (q >> 1) * 8;
                ldsm4(a[mt], sA + (unsigned)((r * 40 + c) * 2));
            }
            #pragma unroll
            for (int n2 = 0; n2 < 2; n2++) {
                int r = ks * 16 + (q & 1) * 8 + l7, c = wn * 32 + n2 * 16 + (q >> 1) * 8;
                ldsm4t(bb[n2], sB + (unsigned)((r * 136 + c) * 2));
            }
            #pragma unroll
            for (int mt = 0; mt < 4; mt++) {
                mmaf(acc[mt][0], a[mt], bb[0]); mmaf(acc[mt][1], a[mt], bb[0] + 2);
                mmaf(acc[mt][2], a[mt], bb[1]); mmaf(acc[mt][3], a[mt], bb[1] + 2);
            }
        }
        __syncthreads();
    }
    #pragma unroll
    for (int mt = 0; mt < 4; mt++)
        #pragma unroll
        for (int nt = 0; nt < 4; nt++) {
            int r = m0 + wm * 64 + mt * 16 + (lane >> 2);
            int c = n0 + wn * 32 + nt * 8 + (lane & 3) * 2;
            float2 bv = *(const float2*)(g_br + c);
            *(__half2*)(g_embW + (size_t)r * 2048 + c) =
                __floats2half2_rn(acc[mt][nt][0] + bv.x, acc[mt][nt][1] + bv.y);
            *(__half2*)(g_embW + (size_t)(r + 8) * 2048 + c) =
                __floats2half2_rn(acc[mt][nt][2] + bv.x, acc[mt][nt][3] + bv.y);
        }
}

// ---------- recurrence: persistent 128 CTAs, Wh slice SMEM-resident ----------
__global__ __launch_bounds__(256) void lstm_kernel(const int* __restrict__ sentence) {
    extern __shared__ __align__(16) char smem[];
    __half* whs = (__half*)smem;                    // [512][136]
    __half* hs  = (__half*)(smem + 139264);         // [16][520]
    float*  zs  = (float*)(smem + 155904);          // [16][132]
    float*  cs  = (float*)(smem + 164352);          // [16][32]
    int tid = threadIdx.x, lane = tid & 31, w = tid >> 5;
    int g = blockIdx.x >> 4, m = blockIdx.x & 15;
    #pragma unroll 4
    for (int i = 0; i < 32; i++) {
        int idx = tid + i * 256; int k = idx >> 4, c = (idx & 15) * 8;
        *(uint4*)(whs + k * 136 + c) = *(const uint4*)(g_Whr + (size_t)k * 2048 + m * 128 + c);
    }
    cs[tid] = 0.f; cs[tid + 256] = 0.f;
    __syncthreads();
    unsigned sH = su(hs), sW = su(whs);
    int q = lane >> 3, l7 = lane & 7;
    const int r16 = tid >> 4, c8 = (tid & 15) * 8;
    for (int t = 0; t < 512; t++) {
        if (tid == 0 && t) {
            while (atomicAdd(&g_cnt[g], 0u) < (unsigned)(16 * t)) __nanosleep(64);
        }
        __syncthreads();
        { // prefetch x-projection (embW gather) into zs
            int tok = sentence[(g * 16 + r16) * 512 + t];
            uint4 v = *(const uint4*)(g_embW + (size_t)tok * 2048 + m * 128 + c8);
            __half2* hp = (__half2*)&v;
            float* zp = zs + r16 * 132 + c8;
            #pragma unroll
            for (int i = 0; i < 4; i++) {
                float2 f = __half22float2(hp[i]); zp[2 * i] = f.x; zp[2 * i + 1] = f.y;
            }
        }
        const __half* hsrc = g_hbuf + (size_t)(t & 1) * 65536 + (size_t)g * 16 * 512;
        #pragma unroll
        for (int i = 0; i < 4; i++) {
            int idx = tid + i * 256; int r = idx >> 6, c = (idx & 63) * 8;
            uint4 v = __ldcg((const uint4*)(hsrc + r * 512 + c));
            *(uint4*)(hs + r * 520 + c) = v;
        }
        __syncthreads();
        float acc[2][4] = {};
        #pragma unroll 8
        for (int kk = 0; kk < 32; kk++) {
            unsigned a[4], bb[4];
            int k0 = kk * 16;
            { int r = (q & 1) * 8 + l7, c = k0 + (q >> 1) * 8;
              ldsm4(a, sH + (unsigned)((r * 520 + c) * 2)); }
            { int r = k0 + (q & 1) * 8 + l7, c = w * 16 + (q >> 1) * 8;
              ldsm4t(bb, sW + (unsigned)((r * 136 + c) * 2)); }
            mmaf(acc[0], a, bb); mmaf(acc[1], a, bb + 2);
        }
        { // accumulate into zs
            int r = lane >> 2, c = w * 16 + (lane & 3) * 2;
            #pragma unroll
            for (int nf = 0; nf < 2; nf++) {
                zs[r * 132 + c + nf * 8]           += acc[nf][0];
                zs[r * 132 + c + nf * 8 + 1]       += acc[nf][1];
                zs[(r + 8) * 132 + c + nf * 8]     += acc[nf][2];
                zs[(r + 8) * 132 + c + nf * 8 + 1] += acc[nf][3];
            }
        }
        __syncthreads();
        { // gate epilogue: 2 units/thread
            int b = r16, u0 = (tid & 15) * 2;
            __half hh[2];
            #pragma unroll
            for (int e = 0; e < 2; e++) {
                int u = u0 + e; const float* z = zs + b * 132 + u * 4;
                float ii = 1.f / (1.f + expf(-z[0]));
                float ff = 1.f / (1.f + expf(-z[1]));
                float gg = tanhf(z[2]);
                float oo = 1.f / (1.f + expf(-z[3]));
                float c2 = ff * cs[b * 32 + u] + ii * gg;
                cs[b * 32 + u] = c2;
                hh[e] = __float2half_rn(oo * tanhf(c2));
            }
            unsigned hv = (unsigned)__half_as_ushort(hh[0]) |
                          ((unsigned)__half_as_ushort(hh[1]) << 16);
            __stcg((unsigned*)(g_hbuf + (size_t)((t + 1) & 1) * 65536 +
                               (size_t)(g * 16 + b) * 512 + m * 32 + u0), hv);
        }
        __threadfence();
        __syncthreads();
        if (tid == 0) atomicAdd(&g_cnt[g], 1u);
    }
}

// ---------- MLP head: one block per batch row ----------
__global__ void mlp_kernel(const float* __restrict__ W1, const float* __restrict__ b1,
                           const float* __restrict__ W2, const float* __restrict__ b2,
                           const float* __restrict__ W3, const float* __restrict__ b3,
                           float* __restrict__ out) {
    __shared__ float hr[512], h1[128], h2[64];
    int b = blockIdx.x, tid = threadIdx.x;
    #pragma unroll
    for (int i = 0; i < 4; i++)
        hr[tid + i * 128] = __half2float(g_hbuf[(size_t)b * 512 + tid + i * 128]);
    __syncthreads();
    float a = b1[tid];
    for (int k = 0; k < 512; k++) a = fmaf(hr[k], W1[k * 128 + tid], a);
    h1[tid] = fmaxf(a, 0.f);
    __syncthreads();
    if (tid < 64) {
        float a2 = b2[tid];
        for (int k = 0; k < 128; k++) a2 = fmaf(h1[k], W2[k * 64 + tid], a2);
        h2[tid] = fmaxf(a2, 0.f);
    }
    __syncthreads();
    if (tid == 0) {
        float a3 = b3[0];
        for (int k = 0; k < 64; k++) a3 = fmaf(h2[k], W3[k], a3);
        out[b] = 1.f / (1.f + expf(-a3));
    }
}

extern "C" void kernel_launch(void* const* d_in, const int* in_sizes, int n_in,
                              void* d_out, int out_size) {
    const int*   sentence = (const int*)d_in[0];
    const float* emb = (const float*)d_in[1];
    const float* Wx  = (const float*)d_in[2];
    const float* Wh  = (const float*)d_in[3];
    const float* b   = (const float*)d_in[4];
    const float* W1  = (const float*)d_in[5];
    const float* b1  = (const float*)d_in[6];
    const float* W2  = (const float*)d_in[7];
    const float* b2  = (const float*)d_in[8];
    const float* W3  = (const float*)d_in[9];
    const float* b3  = (const float*)d_in[10];
    float* out = (float*)d_out;
    cudaFuncSetAttribute(lstm_kernel, cudaFuncAttributeMaxDynamicSharedMemorySize, 166400);
    prep_kernel<<<512, 256>>>(Wx, Wh, b);
    embw_gemm<<<dim3(16, 250), 256>>>(emb);
    lstm_kernel<<<128, 256, 166400>>>(sentence);
    mlp_kernel<<<128, 128>>>(W1, b1, W2, b2, W3, b3, out);
}

// round 6
// speedup vs baseline: 1.3799x; 1.3799x over previous
#include <cuda_runtime.h>
#include <cuda_fp16.h>
#include <math.h>

// dims: VOCAB=32000 E=256 U=512 4U=2048 T=512 B=128
// LSTM partition: 8 groups x 16 CTAs; CTA = 16 batch rows x 128 gate cols (32 units)

__device__ __align__(16) __half g_embW[32000u * 2048u];  // emb@Wx+b, cols permuted u*4+gate
__device__ __align__(16) __half g_embh[32000u * 256u];   // emb in fp16
__device__ __align__(16) __half g_Wxr[256 * 2048];       // Wx permuted, fp16
__device__ __align__(16) __half g_Whr[512 * 2048];       // Wh permuted, fp16
__device__ __align__(16) float  g_br[2048];              // b permuted
__device__ __align__(16) __half g_hbuf[2 * 128 * 512];   // double-buffered h
__device__ unsigned g_cnt[8];                            // per-group step counters

static __device__ __forceinline__ unsigned su(const void* p) {
    return (unsigned)__cvta_generic_to_shared(p);
}
static __device__ __forceinline__ void ldsm4(unsigned* r, unsigned a) {
    asm volatile("ldmatrix.sync.aligned.m8n8.x4.shared.b16 {%0,%1,%2,%3}, [%4];\n"
        : "=r"(r[0]), "=r"(r[1]), "=r"(r[2]), "=r"(r[3]) : "r"(a));
}
static __device__ __forceinline__ void ldsm4t(unsigned* r, unsigned a) {
    asm volatile("ldmatrix.sync.aligned.m8n8.x4.trans.shared.b16 {%0,%1,%2,%3}, [%4];\n"
        : "=r"(r[0]), "=r"(r[1]), "=r"(r[2]), "=r"(r[3]) : "r"(a));
}
static __device__ __forceinline__ void mmaf(float* d, const unsigned* a, const unsigned* b) {
    asm volatile("mma.sync.aligned.m16n8k16.row.col.f32.f16.f16.f32 "
        "{%0,%1,%2,%3}, {%4,%5,%6,%7}, {%8,%9}, {%0,%1,%2,%3};\n"
        : "+f"(d[0]), "+f"(d[1]), "+f"(d[2]), "+f"(d[3])
        : "r"(a[0]), "r"(a[1]), "r"(a[2]), "r"(a[3]), "r"(b[0]), "r"(b[1]));
}
static __device__ __forceinline__ float tanh_ap(float x) {
    float r; asm("tanh.approx.f32 %0, %1;" : "=f"(r) : "f"(x)); return r;
}
static __device__ __forceinline__ float sig_ap(float x) {
    return fmaf(tanh_ap(0.5f * x), 0.5f, 0.5f);
}
#define CPA(dst, src) asm volatile("cp.async.ca.shared.global [%0], [%1], 16;\n" :: "r"(dst), "l"(src))

// ---------- prep: permute weights to fp16, convert emb, zero state ----------
__global__ void prep_kernel(const float* __restrict__ emb, const float* __restrict__ Wx,
                            const float* __restrict__ Wh, const float* __restrict__ b) {
    int tid = blockIdx.x * blockDim.x + threadIdx.x, nth = gridDim.x * blockDim.x;
    for (int i = tid; i < 32000 * 128; i += nth) {   // emb -> fp16, 2 elems/iter
        float2 v = *(const float2*)(emb + (size_t)i * 2);
        *(__half2*)(g_embh + (size_t)i * 2) = __floats2half2_rn(v.x, v.y);
    }
    for (int i = tid; i < 256 * 2048; i += nth) {
        int k = i >> 11, j = i & 2047, u = j >> 2, gt = j & 3;
        g_Wxr[i] = __float2half_rn(Wx[k * 2048 + gt * 512 + u]);
    }
    for (int i = tid; i < 512 * 2048; i += nth) {
        int k = i >> 11, j = i & 2047, u = j >> 2, gt = j & 3;
        g_Whr[i] = __float2half_rn(Wh[k * 2048 + gt * 512 + u]);
    }
    for (int i = tid; i < 2048; i += nth) { int u = i >> 2, gt = i & 3; g_br[i] = b[gt * 512 + u]; }
    for (int i = tid; i < 2 * 128 * 512; i += nth) g_hbuf[i] = __float2half_rn(0.f);
    if (tid < 8) g_cnt[tid] = 0u;
}

// ---------- embW = embh @ Wxr + br : CTA 128x128, K=256, cp.async double-buffered ----------
__global__ __launch_bounds__(256) void embw_gemm() {
    __shared__ __align__(16) __half As[2][128 * 40];
    __shared__ __align__(16) __half Bs[2][32 * 136];
    int tid = threadIdx.x, lane = tid & 31, w = tid >> 5, wm = w >> 2, wn = w & 3;
    int m0 = blockIdx.y * 128, n0 = blockIdx.x * 128;
    float acc[4][4][4];
    #pragma unroll
    for (int i = 0; i < 4; i++)
        #pragma unroll
        for (int j = 0; j < 4; j++)
            #pragma unroll
            for (int k = 0; k < 4; k++) acc[i][j][k] = 0.f;
    int q = lane >> 3, l7 = lane & 7;

    // async loaders: 2 A-chunks + 2 B-chunks per thread per tile
    auto issue = [&](int kt, int buf) {
        int k0 = kt * 32;
        unsigned sAb = su(As[buf]), sBb = su(Bs[buf]);
        #pragma unroll
        for (int i = 0; i < 2; i++) {
            int idx = tid + i * 256;                 // A: 512 chunks
            int r = idx >> 2, cc = (idx & 3) * 8;
            CPA(sAb + (unsigned)((r * 40 + cc) * 2),
                g_embh + (size_t)(m0 + r) * 256 + k0 + cc);
        }
        #pragma unroll
        for (int i = 0; i < 2; i++) {
            int idx = tid + i * 256;                 // B: 512 chunks
            int r = idx >> 4, cc = (idx & 15) * 8;
            CPA(sBb + (unsigned)((r * 136 + cc) * 2),
                g_Wxr + (size_t)(k0 + r) * 2048 + n0 + cc);
        }
        asm volatile("cp.async.commit_group;\n");
    };

    issue(0, 0);
    for (int kt = 0; kt < 8; kt++) {
        int buf = kt & 1;
        if (kt < 7) { issue(kt + 1, buf ^ 1); asm volatile("cp.async.wait_group 1;\n"); }
        else        { asm volatile("cp.async.wait_group 0;\n"); }
        __syncthreads();
        unsigned sA = su(As[buf]), sB = su(Bs[buf]);
        #pragma unroll
        for (int ks = 0; ks < 2; ks++) {
            unsigned a[4][4], bb[2][4];
            #pragma unroll
            for (int mt = 0; mt < 4; mt++) {
                int r = wm * 64 + mt * 16 + (q & 1) * 8 + l7, c = ks * 16 + (q >> 1) * 8;
                ldsm4(a[mt], sA + (unsigned)((r * 40 + c) * 2));
            }
            #pragma unroll
            for (int n2 = 0; n2 < 2; n2++) {
                int r = ks * 16 + (q & 1) * 8 + l7, c = wn * 32 + n2 * 16 + (q >> 1) * 8;
                ldsm4t(bb[n2], sB + (unsigned)((r * 136 + c) * 2));
            }
            #pragma unroll
            for (int mt = 0; mt < 4; mt++) {
                mmaf(acc[mt][0], a[mt], bb[0]); mmaf(acc[mt][1], a[mt], bb[0] + 2);
                mmaf(acc[mt][2], a[mt], bb[1]); mmaf(acc[mt][3], a[mt], bb[1] + 2);
            }
        }
        __syncthreads();
    }
    #pragma unroll
    for (int mt = 0; mt < 4; mt++)
        #pragma unroll
        for (int nt = 0; nt < 4; nt++) {
            int r = m0 + wm * 64 + mt * 16 + (lane >> 2);
            int c = n0 + wn * 32 + nt * 8 + (lane & 3) * 2;
            float2 bv = *(const float2*)(g_br + c);
            *(__half2*)(g_embW + (size_t)r * 2048 + c) =
                __floats2half2_rn(acc[mt][nt][0] + bv.x, acc[mt][nt][1] + bv.y);
            *(__half2*)(g_embW + (size_t)(r + 8) * 2048 + c) =
                __floats2half2_rn(acc[mt][nt][2] + bv.x, acc[mt][nt][3] + bv.y);
        }
}

// ---------- recurrence: persistent 128 CTAs, Wh slice SMEM-resident ----------
__global__ __launch_bounds__(256) void lstm_kernel(const int* __restrict__ sentence) {
    extern __shared__ __align__(16) char smem[];
    __half* whs = (__half*)smem;                    // [512][136]
    __half* hs  = (__half*)(smem + 139264);         // [16][520]
    float*  zs  = (float*)(smem + 155904);          // [16][132]
    int tid = threadIdx.x, lane = tid & 31, w = tid >> 5;
    int g = blockIdx.x >> 4, m = blockIdx.x & 15;
    #pragma unroll 4
    for (int i = 0; i < 32; i++) {
        int idx = tid + i * 256; int k = idx >> 4, c = (idx & 15) * 8;
        *(uint4*)(whs + k * 136 + c) = *(const uint4*)(g_Whr + (size_t)k * 2048 + m * 128 + c);
    }
    unsigned sH = su(hs), sW = su(whs);
    int q = lane >> 3, l7 = lane & 7;
    const int r16 = tid >> 4, c8 = (tid & 15) * 8;
    const int b = r16, u0 = (tid & 15) * 2;
    float cst0 = 0.f, cst1 = 0.f;                   // cell state in regs

    // preload + stage x for t=0
    {
        int tok = sentence[(g * 16 + r16) * 512];
        uint4 v = *(const uint4*)(g_embW + (size_t)tok * 2048 + m * 128 + c8);
        __half2* hp = (__half2*)&v;
        float* zp = zs + r16 * 132 + c8;
        #pragma unroll
        for (int i = 0; i < 4; i++) {
            float2 f = __half22float2(hp[i]); zp[2 * i] = f.x; zp[2 * i + 1] = f.y;
        }
    }
    __syncthreads();

    for (int t = 0; t < 512; t++) {
        if (tid == 0 && t) {
            unsigned target = (unsigned)(16 * t), v;
            do {
                asm volatile("ld.acquire.gpu.global.u32 %0, [%1];" : "=r"(v) : "l"(&g_cnt[g]));
                if (v >= target) break;
                __nanosleep(32);
            } while (1);
        }
        __syncthreads();
        // load h(t) tile from L2 into smem
        const __half* hsrc = g_hbuf + (size_t)(t & 1) * 65536 + (size_t)g * 16 * 512;
        #pragma unroll
        for (int i = 0; i < 4; i++) {
            int idx = tid + i * 256; int r = idx >> 6, c = (idx & 63) * 8;
            uint4 v = __ldcg((const uint4*)(hsrc + r * 512 + c));
            *(uint4*)(hs + r * 520 + c) = v;
        }
        // prefetch x for t+1 (off critical path: consumed after next sync cycle)
        uint4 xv;
        {
            int tn = (t + 1 < 512) ? t + 1 : 511;
            int tok = sentence[(g * 16 + r16) * 512 + tn];
            xv = *(const uint4*)(g_embW + (size_t)tok * 2048 + m * 128 + c8);
        }
        __syncthreads();
        float acc[2][4] = {};
        #pragma unroll 8
        for (int kk = 0; kk < 32; kk++) {
            unsigned a[4], bb[4];
            int k0 = kk * 16;
            { int r = (q & 1) * 8 + l7, c = k0 + (q >> 1) * 8;
              ldsm4(a, sH + (unsigned)((r * 520 + c) * 2)); }
            { int r = k0 + (q & 1) * 8 + l7, c = w * 16 + (q >> 1) * 8;
              ldsm4t(bb, sW + (unsigned)((r * 136 + c) * 2)); }
            mmaf(acc[0], a, bb); mmaf(acc[1], a, bb + 2);
        }
        { // accumulate h@Wh into zs (x already staged there)
            int r = lane >> 2, c = w * 16 + (lane & 3) * 2;
            #pragma unroll
            for (int nf = 0; nf < 2; nf++) {
                zs[r * 132 + c + nf * 8]           += acc[nf][0];
                zs[r * 132 + c + nf * 8 + 1]       += acc[nf][1];
                zs[(r + 8) * 132 + c + nf * 8]     += acc[nf][2];
                zs[(r + 8) * 132 + c + nf * 8 + 1] += acc[nf][3];
            }
        }
        __syncthreads();
        { // gate epilogue: 2 units/thread, HW tanh, c in regs
            const float* z0 = zs + b * 132 + u0 * 4;
            float i0 = sig_ap(z0[0]), f0 = sig_ap(z0[1]);
            float g0 = tanh_ap(z0[2]), o0 = sig_ap(z0[3]);
            cst0 = f0 * cst0 + i0 * g0;
            float h0 = o0 * tanh_ap(cst0);
            float i1 = sig_ap(z0[4]), f1 = sig_ap(z0[5]);
            float g1 = tanh_ap(z0[6]), o1 = sig_ap(z0[7]);
            cst1 = f1 * cst1 + i1 * g1;
            float h1 = o1 * tanh_ap(cst1);
            __half2 hh = __floats2half2_rn(h0, h1);
            __stcg((unsigned*)(g_hbuf + (size_t)((t + 1) & 1) * 65536 +
                               (size_t)(g * 16 + b) * 512 + m * 32 + u0),
                   *(unsigned*)&hh);
        }
        __syncthreads();
        // stage x(t+1) into zs (zs fully consumed above)
        if (t + 1 < 512) {
            __half2* hp = (__half2*)&xv;
            float* zp = zs + r16 * 132 + c8;
            #pragma unroll
            for (int i = 0; i < 4; i++) {
                float2 f = __half22float2(hp[i]); zp[2 * i] = f.x; zp[2 * i + 1] = f.y;
            }
        }
        if (tid == 0) { __threadfence(); atomicAdd(&g_cnt[g], 1u); }
    }
}

// ---------- MLP head: one block per batch row ----------
__global__ void mlp_kernel(const float* __restrict__ W1, const float* __restrict__ b1,
                           const float* __restrict__ W2, const float* __restrict__ b2,
                           const float* __restrict__ W3, const float* __restrict__ b3,
                           float* __restrict__ out) {
    __shared__ float hr[512], h1[128], h2[64];
    int b = blockIdx.x, tid = threadIdx.x;
    #pragma unroll
    for (int i = 0; i < 4; i++)
        hr[tid + i * 128] = __half2float(g_hbuf[(size_t)b * 512 + tid + i * 128]);
    __syncthreads();
    float a0 = 0.f, a1 = 0.f, a2 = 0.f, a3 = 0.f;
    for (int k = 0; k < 512; k += 4) {
        a0 = fmaf(hr[k],     W1[k * 128 + tid],       a0);
        a1 = fmaf(hr[k + 1], W1[(k + 1) * 128 + tid], a1);
        a2 = fmaf(hr[k + 2], W1[(k + 2) * 128 + tid], a2);
        a3 = fmaf(hr[k + 3], W1[(k + 3) * 128 + tid], a3);
    }
    h1[tid] = fmaxf(b1[tid] + (a0 + a1) + (a2 + a3), 0.f);
    __syncthreads();
    if (tid < 64) {
        float s0 = 0.f, s1 = 0.f;
        for (int k = 0; k < 128; k += 2) {
            s0 = fmaf(h1[k],     W2[k * 64 + tid],       s0);
            s1 = fmaf(h1[k + 1], W2[(k + 1) * 64 + tid], s1);
        }
        h2[tid] = fmaxf(b2[tid] + s0 + s1, 0.f);
    }
    __syncthreads();
    if (tid == 0) {
        float a3s = b3[0];
        for (int k = 0; k < 64; k++) a3s = fmaf(h2[k], W3[k], a3s);
        out[b] = 1.f / (1.f + __expf(-a3s));
    }
}

extern "C" void kernel_launch(void* const* d_in, const int* in_sizes, int n_in,
                              void* d_out, int out_size) {
    const int*   sentence = (const int*)d_in[0];
    const float* emb = (const float*)d_in[1];
    const float* Wx  = (const float*)d_in[2];
    const float* Wh  = (const float*)d_in[3];
    const float* b   = (const float*)d_in[4];
    const float* W1  = (const float*)d_in[5];
    const float* b1  = (const float*)d_in[6];
    const float* W2  = (const float*)d_in[7];
    const float* b2  = (const float*)d_in[8];
    const float* W3  = (const float*)d_in[9];
    const float* b3  = (const float*)d_in[10];
    float* out = (float*)d_out;
    cudaFuncSetAttribute(lstm_kernel, cudaFuncAttributeMaxDynamicSharedMemorySize, 164352);
    prep_kernel<<<512, 256>>>(emb, Wx, Wh, b);
    embw_gemm<<<dim3(16, 250), 256>>>();
    lstm_kernel<<<128, 256, 164352>>>(sentence);
    mlp_kernel<<<128, 128>>>(W1, b1, W2, b2, W3, b3, out);
}

// round 9
// speedup vs baseline: 1.4056x; 1.0187x over previous
#include <cuda_runtime.h>
#include <cuda_fp16.h>
#include <math.h>

// dims: VOCAB=32000 E=256 U=512 4U=2048 T=512 B=128
// LSTM partition: 8 groups x 16 CTAs; CTA = 16 batch rows x 128 gate cols (32 units)
// Wh fragments register-resident across all 512 steps (time-invariant B operand).

__device__ __align__(16) __half g_embW[32000u * 2048u];  // emb@Wx+b, cols permuted u*4+gate
__device__ __align__(16) __half g_embh[32000u * 256u];   // emb fp16
__device__ __align__(16) __half g_Wxr[256 * 2048];       // Wx permuted fp16
__device__ __align__(16) __half g_Whr[512 * 2048];       // Wh permuted fp16
__device__ __align__(16) float  g_br[2048];
__device__ __align__(16) __half g_hbuf[2 * 128 * 512];   // double-buffered h
__device__ unsigned g_cnt[8];

static __device__ __forceinline__ unsigned su(const void* p) {
    return (unsigned)__cvta_generic_to_shared(p);
}
static __device__ __forceinline__ void ldsm4(unsigned* r, unsigned a) {
    asm volatile("ldmatrix.sync.aligned.m8n8.x4.shared.b16 {%0,%1,%2,%3}, [%4];\n"
        : "=r"(r[0]), "=r"(r[1]), "=r"(r[2]), "=r"(r[3]) : "r"(a));
}
static __device__ __forceinline__ void ldsm4t(unsigned* r, unsigned a) {
    asm volatile("ldmatrix.sync.aligned.m8n8.x4.trans.shared.b16 {%0,%1,%2,%3}, [%4];\n"
        : "=r"(r[0]), "=r"(r[1]), "=r"(r[2]), "=r"(r[3]) : "r"(a));
}
static __device__ __forceinline__ void mmaf(float* d, const unsigned* a, const unsigned* b) {
    asm volatile("mma.sync.aligned.m16n8k16.row.col.f32.f16.f16.f32 "
        "{%0,%1,%2,%3}, {%4,%5,%6,%7}, {%8,%9}, {%0,%1,%2,%3};\n"
        : "+f"(d[0]), "+f"(d[1]), "+f"(d[2]), "+f"(d[3])
        : "r"(a[0]), "r"(a[1]), "r"(a[2]), "r"(a[3]), "r"(b[0]), "r"(b[1]));
}
static __device__ __forceinline__ float tanh_ap(float x) {
    float r; asm("tanh.approx.f32 %0, %1;" : "=f"(r) : "f"(x)); return r;
}
static __device__ __forceinline__ float sig_ap(float x) {
    return fmaf(tanh_ap(0.5f * x), 0.5f, 0.5f);
}
#define CPA(dst, src) asm volatile("cp.async.ca.shared.global [%0], [%1], 16;\n" :: "r"(dst), "l"(src))

// ---------- prep: permute weights to fp16, convert emb, zero state ----------
__global__ void prep_kernel(const float* __restrict__ emb, const float* __restrict__ Wx,
                            const float* __restrict__ Wh, const float* __restrict__ b) {
    int tid = blockIdx.x * blockDim.x + threadIdx.x, nth = gridDim.x * blockDim.x;
    for (int i = tid; i < 32000 * 128; i += nth) {
        float2 v = *(const float2*)(emb + (size_t)i * 2);
        *(__half2*)(g_embh + (size_t)i * 2) = __floats2half2_rn(v.x, v.y);
    }
    for (int i = tid; i < 256 * 2048; i += nth) {
        int k = i >> 11, j = i & 2047, u = j >> 2, gt = j & 3;
        g_Wxr[i] = __float2half_rn(Wx[k * 2048 + gt * 512 + u]);
    }
    for (int i = tid; i < 512 * 2048; i += nth) {
        int k = i >> 11, j = i & 2047, u = j >> 2, gt = j & 3;
        g_Whr[i] = __float2half_rn(Wh[k * 2048 + gt * 512 + u]);
    }
    for (int i = tid; i < 2048; i += nth) { int u = i >> 2, gt = i & 3; g_br[i] = b[gt * 512 + u]; }
    for (int i = tid; i < 2 * 128 * 512; i += nth) g_hbuf[i] = __float2half_rn(0.f);
    if (tid < 8) g_cnt[tid] = 0u;
}

// ---------- embW = embh @ Wxr + br : CTA 128x128, K=256, cp.async double-buffered ----------
__global__ __launch_bounds__(256) void embw_gemm() {
    __shared__ __align__(16) __half As[2][128 * 40];
    __shared__ __align__(16) __half Bs[2][32 * 136];
    int tid = threadIdx.x, lane = tid & 31, w = tid >> 5, wm = w >> 2, wn = w & 3;
    int m0 = blockIdx.y * 128, n0 = blockIdx.x * 128;
    float acc[4][4][4];
    #pragma unroll
    for (int i = 0; i < 4; i++)
        #pragma unroll
        for (int j = 0; j < 4; j++)
            #pragma unroll
            for (int k = 0; k < 4; k++) acc[i][j][k] = 0.f;
    int q = lane >> 3, l7 = lane & 7;
    auto issue = [&](int kt, int buf) {
        int k0 = kt * 32;
        unsigned sAb = su(As[buf]), sBb = su(Bs[buf]);
        #pragma unroll
        for (int i = 0; i < 2; i++) {
            int idx = tid + i * 256; int r = idx >> 2, cc = (idx & 3) * 8;
            CPA(sAb + (unsigned)((r * 40 + cc) * 2), g_embh + (size_t)(m0 + r) * 256 + k0 + cc);
        }
        #pragma unroll
        for (int i = 0; i < 2; i++) {
            int idx = tid + i * 256; int r = idx >> 4, cc = (idx & 15) * 8;
            CPA(sBb + (unsigned)((r * 136 + cc) * 2), g_Wxr + (size_t)(k0 + r) * 2048 + n0 + cc);
        }
        asm volatile("cp.async.commit_group;\n");
    };
    issue(0, 0);
    for (int kt = 0; kt < 8; kt++) {
        int buf = kt & 1;
        if (kt < 7) { issue(kt + 1, buf ^ 1); asm volatile("cp.async.wait_group 1;\n"); }
        else        { asm volatile("cp.async.wait_group 0;\n"); }
        __syncthreads();
        unsigned sA = su(As[buf]), sB = su(Bs[buf]);
        #pragma unroll
        for (int ks = 0; ks < 2; ks++) {
            unsigned a[4][4], bb[2][4];
            #pragma unroll
            for (int mt = 0; mt < 4; mt++) {
                int r = wm * 64 + mt * 16 + (q & 1) * 8 + l7, c = ks * 16 + (q >> 1) * 8;
                ldsm4(a[mt], sA + (unsigned)((r * 40 + c) * 2));
            }
            #pragma unroll
            for (int n2 = 0; n2 < 2; n2++) {
                int r = ks * 16 + (q & 1) * 8 + l7, c = wn * 32 + n2 * 16 + (q >> 1) * 8;
                ldsm4t(bb[n2], sB + (unsigned)((r * 136 + c) * 2));
            }
            #pragma unroll
            for (int mt = 0; mt < 4; mt++) {
                mmaf(acc[mt][0], a[mt], bb[0]); mmaf(acc[mt][1], a[mt], bb[0] + 2);
                mmaf(acc[mt][2], a[mt], bb[1]); mmaf(acc[mt][3], a[mt], bb[1] + 2);
            }
        }
        __syncthreads();
    }
    #pragma unroll
    for (int mt = 0; mt < 4; mt++)
        #pragma unroll
        for (int nt = 0; nt < 4; nt++) {
            int r = m0 + wm * 64 + mt * 16 + (lane >> 2);
            int c = n0 + wn * 32 + nt * 8 + (lane & 3) * 2;
            float2 bv = *(const float2*)(g_br + c);
            *(__half2*)(g_embW + (size_t)r * 2048 + c) =
                __floats2half2_rn(acc[mt][nt][0] + bv.x, acc[mt][nt][1] + bv.y);
            *(__half2*)(g_embW + (size_t)(r + 8) * 2048 + c) =
                __floats2half2_rn(acc[mt][nt][2] + bv.x, acc[mt][nt][3] + bv.y);
        }
}

// ---------- recurrence: persistent 128 CTAs, Wh fragments in registers ----------
__global__ __launch_bounds__(256, 1) void lstm_kernel(const int* __restrict__ sentence) {
    extern __shared__ __align__(16) char smem[];
    __half* whs = (__half*)smem;                    // [512][136]  (init-only, B preload)
    __half* hs  = (__half*)(smem + 139264);         // [16][520]
    float*  zs  = (float*)(smem + 155904);          // [16][132]
    int tid = threadIdx.x, lane = tid & 31, w = tid >> 5;
    int g = blockIdx.x >> 4, m = blockIdx.x & 15;
    #pragma unroll 4
    for (int i = 0; i < 32; i++) {
        int idx = tid + i * 256; int k = idx >> 4, c = (idx & 15) * 8;
        *(uint4*)(whs + k * 136 + c) = *(const uint4*)(g_Whr + (size_t)k * 2048 + m * 128 + c);
    }
    unsigned sH = su(hs), sW = su(whs);
    int q = lane >> 3, l7 = lane & 7;
    const int r16 = tid >> 4, c8 = (tid & 15) << 3;
    const int b = r16, u0 = (tid & 15) << 1;
    float cst0 = 0.f, cst1 = 0.f;

    // stage x(0) into zs
    {
        int tok = sentence[(g * 16 + r16) * 512];
        uint4 v = *(const uint4*)(g_embW + (size_t)tok * 2048 + m * 128 + c8);
        __half2* hp = (__half2*)&v;
        float* zp = zs + r16 * 132 + c8;
        #pragma unroll
        for (int i = 0; i < 4; i++) {
            float2 f = __half22float2(hp[i]); zp[2 * i] = f.x; zp[2 * i + 1] = f.y;
        }
    }
    __syncthreads();

    // Preload Wh B-fragments for this warp's 16 gate cols, all K: 32 x ldsm4t -> 128 regs
    unsigned Bf[32][4];
    #pragma unroll
    for (int kk = 0; kk < 32; kk++) {
        int r = kk * 16 + (q & 1) * 8 + l7, c = w * 16 + (q >> 1) * 8;
        ldsm4t(Bf[kk], sW + (unsigned)((r * 136 + c) * 2));
    }

    for (int t = 0; t < 512; t++) {
        if (t && lane == 0) {
            unsigned tgt = 16u * (unsigned)t, v;
            do { asm volatile("ld.acquire.gpu.global.u32 %0, [%1];" : "=r"(v) : "l"(&g_cnt[g])); } while (v < tgt);
        }
        __syncwarp();
        // stage h(t) tile from L2 into smem
        const __half* hsrc = g_hbuf + (size_t)(t & 1) * 65536 + (size_t)g * 16 * 512;
        #pragma unroll
        for (int i = 0; i < 4; i++) {
            int idx = tid + i * 256; int r = idx >> 6, c = (idx & 63) * 8;
            uint4 v = __ldcg((const uint4*)(hsrc + r * 512 + c));
            *(uint4*)(hs + r * 520 + c) = v;
        }
        // prefetch x(t+1)
        uint4 xv;
        { int tn = (t + 1 < 512) ? t + 1 : 511;
          int tok = sentence[(g * 16 + r16) * 512 + tn];
          xv = *(const uint4*)(g_embW + (size_t)tok * 2048 + m * 128 + c8); }
        __syncthreads();
        float acc[2][4] = {};
        #pragma unroll
        for (int kk = 0; kk < 32; kk++) {
            unsigned a[4];
            int r = (q & 1) * 8 + l7, c = kk * 16 + (q >> 1) * 8;
            ldsm4(a, sH + (unsigned)((r * 520 + c) * 2));
            mmaf(acc[0], a, Bf[kk]); mmaf(acc[1], a, Bf[kk] + 2);
        }
        { // accumulate h@Wh into zs (x already staged there)
            int r = lane >> 2, c = w * 16 + (lane & 3) * 2;
            #pragma unroll
            for (int nf = 0; nf < 2; nf++) {
                zs[r * 132 + c + nf * 8]           += acc[nf][0];
                zs[r * 132 + c + nf * 8 + 1]       += acc[nf][1];
                zs[(r + 8) * 132 + c + nf * 8]     += acc[nf][2];
                zs[(r + 8) * 132 + c + nf * 8 + 1] += acc[nf][3];
            }
        }
        __syncthreads();
        { // gate epilogue: 2 units/thread, HW tanh, c in regs
            const float* z0 = zs + b * 132 + u0 * 4;
            float i0 = sig_ap(z0[0]), f0 = sig_ap(z0[1]);
            float g0 = tanh_ap(z0[2]), o0 = sig_ap(z0[3]);
            cst0 = f0 * cst0 + i0 * g0;
            float h0 = o0 * tanh_ap(cst0);
            float i1 = sig_ap(z0[4]), f1 = sig_ap(z0[5]);
            float g1 = tanh_ap(z0[6]), o1 = sig_ap(z0[7]);
            cst1 = f1 * cst1 + i1 * g1;
            float h1 = o1 * tanh_ap(cst1);
            __half2 hh = __floats2half2_rn(h0, h1);
            __stcg((unsigned*)(g_hbuf + (size_t)((t + 1) & 1) * 65536 +
                               (size_t)(g * 16 + b) * 512 + m * 32 + u0), *(unsigned*)&hh);
        }
        __syncthreads();
        if (tid == 0)
            asm volatile("red.release.gpu.global.add.u32 [%0], %1;" :: "l"(&g_cnt[g]), "r"(1u) : "memory");
        if (t + 1 < 512) { // stage x(t+1) into zs (zs fully consumed above)
            __half2* hp = (__half2*)&xv;
            float* zp = zs + r16 * 132 + c8;
            #pragma unroll
            for (int i = 0; i < 4; i++) {
                float2 f = __half22float2(hp[i]); zp[2 * i] = f.x; zp[2 * i + 1] = f.y;
            }
        }
    }
}

// ---------- MLP head: one block per batch row ----------
__global__ void mlp_kernel(const float* __restrict__ W1, const float* __restrict__ b1,
                           const float* __restrict__ W2, const float* __restrict__ b2,
                           const float* __restrict__ W3, const float* __restrict__ b3,
                           float* __restrict__ out) {
    __shared__ float hr[512], h1[128], h2[64];
    int b = blockIdx.x, tid = threadIdx.x;
    #pragma unroll
    for (int i = 0; i < 4; i++)
        hr[tid + i * 128] = __half2float(g_hbuf[(size_t)b * 512 + tid + i * 128]);
    __syncthreads();
    float a0 = 0.f, a1 = 0.f, a2 = 0.f, a3 = 0.f;
    #pragma unroll 2
    for (int k = 0; k < 512; k += 4) {
        a0 = fmaf(hr[k],     W1[k * 128 + tid],       a0);
        a1 = fmaf(hr[k + 1], W1[(k + 1) * 128 + tid], a1);
        a2 = fmaf(hr[k + 2], W1[(k + 2) * 128 + tid], a2);
        a3 = fmaf(hr[k + 3], W1[(k + 3) * 128 + tid], a3);
    }
    h1[tid] = fmaxf(b1[tid] + (a0 + a1) + (a2 + a3), 0.f);
    __syncthreads();
    if (tid < 64) {
        float s0 = 0.f, s1 = 0.f;
        for (int k = 0; k < 128; k += 2) {
            s0 = fmaf(h1[k],     W2[k * 64 + tid],       s0);
            s1 = fmaf(h1[k + 1], W2[(k + 1) * 64 + tid], s1);
        }
        h2[tid] = fmaxf(b2[tid] + s0 + s1, 0.f);
    }
    __syncthreads();
    if (tid == 0) {
        float a3s = b3[0];
        for (int k = 0; k < 64; k++) a3s = fmaf(h2[k], W3[k], a3s);
        out[b] = 1.f / (1.f + __expf(-a3s));
    }
}

extern "C" void kernel_launch(void* const* d_in, const int* in_sizes, int n_in,
                              void* d_out, int out_size) {
    const int*   sentence = (const int*)d_in[0];
    const float* emb = (const float*)d_in[1];
    const float* Wx  = (const float*)d_in[2];
    const float* Wh  = (const float*)d_in[3];
    const float* b   = (const float*)d_in[4];
    const float* W1  = (const float*)d_in[5];
    const float* b1  = (const float*)d_in[6];
    const float* W2  = (const float*)d_in[7];
    const float* b2  = (const float*)d_in[8];
    const float* W3  = (const float*)d_in[9];
    const float* b3  = (const float*)d_in[10];
    float* out = (float*)d_out;
    cudaFuncSetAttribute(lstm_kernel, cudaFuncAttributeMaxDynamicSharedMemorySize, 164352);
    prep_kernel<<<512, 256>>>(emb, Wx, Wh, b);
    embw_gemm<<<dim3(16, 250), 256>>>();
    lstm_kernel<<<128, 256, 164352>>>(sentence);
    mlp_kernel<<<128, 128>>>(W1, b1, W2, b2, W3, b3, out);
}